// round 7
// baseline (speedup 1.0000x reference)
#include <cuda_runtime.h>
#include <cstdint>
#include <cstddef>

typedef unsigned long long ull;

#define Tlen 512
#define NB   4096
#define NTHR 512   // 16 warps; warp w owns units [w*25/16, (w+1)*25/16)

// ---- shared memory layout (float offsets), all 16B-aligned ----
#define W0_OFF    0                    // 100 rows x 28  = 2800  : L1 fused [Wih1|Whh1|pad2]
#define W123_OFF  2800                 // 3 x 100 x 52   = 15600 : L2-4 fused [Wih|0|Whh|0]
#define BIAS_OFF  (W123_OFF + 15600)   // 18400 : [4 layer][25 unit][4 gate] fused bih+bhh
#define WFC_OFF   (BIAS_OFF + 400)     // 18800 : 52-float fc row (W_fc at [26..50])
#define V0_OFF    (WFC_OFF + 52)       // 18852 : [2 buf][32 lane][28]  L1 v-rows
#define V123_OFF  (V0_OFF + 1792)      // 20644 : [3 layer][2 buf][32][52]
#define SMEM_FLOATS (V123_OFF + 9984)  // 30628 floats = 122512 bytes

__device__ __forceinline__ ull pack2(float lo, float hi) {
    return (ull)__float_as_uint(lo) | ((ull)__float_as_uint(hi) << 32);
}
__device__ __forceinline__ float hsum2(ull v) {
    float lo = __uint_as_float((unsigned)v);
    float hi = __uint_as_float((unsigned)(v >> 32));
    return lo + hi;
}
__device__ __forceinline__ void fma2(ull& acc, ull a, ull b) {
    asm("fma.rn.f32x2 %0, %1, %2, %0;" : "+l"(acc) : "l"(a), "l"(b));
}
__device__ __forceinline__ float fast_sig(float x) {
    float e, r;
    asm("ex2.approx.ftz.f32 %0, %1;" : "=f"(e) : "f"(x * -1.4426950408889634f));
    asm("rcp.approx.ftz.f32 %0, %1;" : "=f"(r) : "f"(e + 1.0f));
    return r;
}
__device__ __forceinline__ float fast_tanh(float x) {
    return fmaf(2.0f, fast_sig(2.0f * x), -1.0f);
}

// 4-gate dot products for one unit, v-row already in registers.
template<int NCH>
__device__ __forceinline__ void gates4reg(const ulonglong2* __restrict__ V,
    const float* __restrict__ w0, const float* __restrict__ w1,
    const float* __restrict__ w2, const float* __restrict__ w3,
    float b0, float b1, float b2, float b3,
    float& s0, float& s1, float& s2, float& s3)
{
    ull A0 = pack2(b0, 0.f), B0 = 0ull;
    ull A1 = pack2(b1, 0.f), B1 = 0ull;
    ull A2 = pack2(b2, 0.f), B2 = 0ull;
    ull A3 = pack2(b3, 0.f), B3 = 0ull;
    const ulonglong2* W0 = (const ulonglong2*)w0;
    const ulonglong2* W1 = (const ulonglong2*)w1;
    const ulonglong2* W2 = (const ulonglong2*)w2;
    const ulonglong2* W3 = (const ulonglong2*)w3;
#pragma unroll
    for (int ch = 0; ch < NCH; ++ch) {
        ulonglong2 w;
        w = W0[ch]; fma2(A0, w.x, V[ch].x); fma2(B0, w.y, V[ch].y);
        w = W1[ch]; fma2(A1, w.x, V[ch].x); fma2(B1, w.y, V[ch].y);
        w = W2[ch]; fma2(A2, w.x, V[ch].x); fma2(B2, w.y, V[ch].y);
        w = W3[ch]; fma2(A3, w.x, V[ch].x); fma2(B3, w.y, V[ch].y);
    }
    s0 = hsum2(A0) + hsum2(B0);
    s1 = hsum2(A1) + hsum2(B1);
    s2 = hsum2(A2) + hsum2(B2);
    s3 = hsum2(A3) + hsum2(B3);
}

__global__ void __launch_bounds__(NTHR) lstm_kernel(
    const float* __restrict__ x,
    const float* __restrict__ Wih1, const float* __restrict__ Whh1,
    const float* __restrict__ bih1, const float* __restrict__ bhh1,
    const float* __restrict__ Wih2, const float* __restrict__ Whh2,
    const float* __restrict__ bih2, const float* __restrict__ bhh2,
    const float* __restrict__ Wih3, const float* __restrict__ Whh3,
    const float* __restrict__ bih3, const float* __restrict__ bhh3,
    const float* __restrict__ Wih4, const float* __restrict__ Whh4,
    const float* __restrict__ bih4, const float* __restrict__ bhh4,
    const float* __restrict__ Wfc, const float* __restrict__ bfc,
    float* __restrict__ out, int write_states)
{
    extern __shared__ float smem[];
    const int tid = threadIdx.x;

    // ---- stage fused weights ----
    for (int i = tid; i < 2800; i += NTHR) {
        int g = i / 28, p = i - g * 28;
        float v = 0.f;
        if (p == 0)      v = Wih1[g];
        else if (p < 26) v = Whh1[g * 25 + p - 1];
        smem[W0_OFF + i] = v;
    }
    {
        const float* WihL[3] = {Wih2, Wih3, Wih4};
        const float* WhhL[3] = {Whh2, Whh3, Whh4};
        for (int i = tid; i < 15600; i += NTHR) {
            int l = i / 5200; int r = i - l * 5200;
            int g = r / 52,   p = r - g * 52;
            float v = 0.f;
            if (p < 25)                 v = WihL[l][g * 25 + p];
            else if (p >= 26 && p < 51) v = WhhL[l][g * 25 + p - 26];
            smem[W123_OFF + i] = v;
        }
        const float* bi[4] = {bih1, bih2, bih3, bih4};
        const float* bh[4] = {bhh1, bhh2, bhh3, bhh4};
        // bias as [layer][unit][gate] so one float4 covers a unit's 4 gates
        for (int i = tid; i < 400; i += NTHR) {
            int l = i / 100, r = i - l * 100, u = r >> 2, j = r & 3;
            smem[BIAS_OFF + i] = bi[l][j * 25 + u] + bh[l][j * 25 + u];
        }
    }
    for (int i = tid; i < 52; i += NTHR)
        smem[WFC_OFF + i] = (i >= 26 && i < 51) ? Wfc[i - 26] : 0.f;
    for (int i = tid; i < 1792 + 9984; i += NTHR) smem[V0_OFF + i] = 0.f;
    __syncthreads();

    const int lane  = tid & 31;
    const int wid   = tid >> 5;
    const int first = (wid * 25) >> 4;            // owned units: first .. next-1
    const int nu    = (((wid + 1) * 25) >> 4) - first;   // 1 or 2
    const int gb    = (blockIdx.x << 5) + lane;   // global batch element

    float xreg = 0.f, bfc_reg = 0.f;
    if (wid == 0) {
        smem[V0_OFF + lane * 28 + 0] = x[gb];     // x_0 -> buffer 0
        xreg = x[(size_t)NB + gb];                // prefetch x_1
    }
    if (wid == 2) bfc_reg = bfc[0];
    __syncthreads();

    float c[8];                                    // c[layer*2 + slot]
#pragma unroll
    for (int i = 0; i < 8; ++i) c[i] = 0.f;

    float* v0r = smem + V0_OFF   + lane * 28;      // + buf*896
    float* v1r = smem + V123_OFF + lane * 52;      // + buf*1664
    float* v2r = v1r + 3328;
    float* v3r = v2r + 3328;
    const float* biasS = smem + BIAS_OFF;
    const float* wfc   = smem + WFC_OFF;

    for (int t = 0; t < Tlen; ++t) {
        const int cur = t & 1, nxt = cur ^ 1;
        float* v0c = v0r + cur * 896;  float* v0n = v0r + nxt * 896;
        float* v1c = v1r + cur * 1664; float* v1n = v1r + nxt * 1664;
        float* v2c = v2r + cur * 1664; float* v2n = v2r + nxt * 1664;
        float* v3c = v3r + cur * 1664; float* v3n = v3r + nxt * 1664;

        // ---------- phase 1: layer 1 (+ stager, + fc one step behind) ----------
        if (wid == 0) {
            v0n[0] = xreg;                         // x_{t+1}
            int t2 = (t + 2 < Tlen) ? t + 2 : Tlen - 1;
            xreg = x[(size_t)t2 * NB + gb];
        }
        if (wid == 2 && t > 0) {                   // y(t-1) = h4(t-1)@Wfc + bfc
            const ulonglong2* V3 = (const ulonglong2*)v3c;
            const ulonglong2* WF = (const ulonglong2*)wfc;
            ull A = pack2(bfc_reg, 0.f), B = 0ull;
#pragma unroll
            for (int ch = 6; ch < 13; ++ch) {      // wfc zero outside [26..50]
                ulonglong2 hv = V3[ch]; ulonglong2 w = WF[ch];
                fma2(A, w.x, hv.x); fma2(B, w.y, hv.y);
            }
            out[(size_t)(t - 1) * NB + gb] = hsum2(A) + hsum2(B);
        }
        {
            ulonglong2 V[7];
#pragma unroll
            for (int ch = 0; ch < 7; ++ch) V[ch] = ((const ulonglong2*)v0c)[ch];
#pragma unroll
            for (int k = 0; k < 2; ++k) if (k < nu) {
                const int u = first + k;
                const float* wr = smem + W0_OFF + u * 28;
                float4 bb = *(const float4*)(biasS + u * 4);
                float s0, s1, s2, s3;
                gates4reg<7>(V, wr, wr + 700, wr + 1400, wr + 2100,
                             bb.x, bb.y, bb.z, bb.w, s0, s1, s2, s3);
                float fi = fast_sig(s0), ff = fast_sig(s1);
                float fg = fast_tanh(s2), fo = fast_sig(s3);
                c[k] = fmaf(ff, c[k], fi * fg);
                float h = fo * fast_tanh(c[k]);
                v0n[1 + u] = h; v1c[u] = h;
            }
        }
        __syncthreads();

        // ---------- phases 2-4: layers 2-4 ----------
#define LAYER_PHASE(LI, VC, VNSELF, VCHILD)                                     \
        {                                                                       \
            ulonglong2 V[13];                                                   \
            _Pragma("unroll")                                                   \
            for (int ch = 0; ch < 13; ++ch) V[ch] = ((const ulonglong2*)(VC))[ch]; \
            _Pragma("unroll")                                                   \
            for (int k = 0; k < 2; ++k) if (k < nu) {                           \
                const int u = first + k;                                        \
                const float* wr = smem + W123_OFF + (LI - 1) * 5200 + u * 52;   \
                float4 bb = *(const float4*)(biasS + LI * 100 + u * 4);         \
                float s0, s1, s2, s3;                                           \
                gates4reg<13>(V, wr, wr + 1300, wr + 2600, wr + 3900,           \
                              bb.x, bb.y, bb.z, bb.w, s0, s1, s2, s3);          \
                float fi = fast_sig(s0), ff = fast_sig(s1);                     \
                float fg = fast_tanh(s2), fo = fast_sig(s3);                    \
                c[LI * 2 + k] = fmaf(ff, c[LI * 2 + k], fi * fg);               \
                float h = fo * fast_tanh(c[LI * 2 + k]);                        \
                (VNSELF)[26 + u] = h;                                           \
                if (VCHILD) ((float*)(VCHILD))[u] = h;                          \
            }                                                                   \
        }

        LAYER_PHASE(1, v1c, v1n, v2c)
        __syncthreads();
        LAYER_PHASE(2, v2c, v2n, v3c)
        __syncthreads();
        LAYER_PHASE(3, v3c, v3n, (float*)0)
        __syncthreads();
#undef LAYER_PHASE
    }

    // ---- final fc: h4(T-1) is in v3 buffer 0 (Tlen even) ----
    if (wid == 2) {
        const ulonglong2* V3 = (const ulonglong2*)v3r;   // buffer 0
        const ulonglong2* WF = (const ulonglong2*)wfc;
        ull A = pack2(bfc_reg, 0.f), B = 0ull;
#pragma unroll
        for (int ch = 6; ch < 13; ++ch) {
            ulonglong2 hv = V3[ch]; ulonglong2 w = WF[ch];
            fma2(A, w.x, hv.x); fma2(B, w.y, hv.y);
        }
        out[(size_t)(Tlen - 1) * NB + gb] = hsum2(A) + hsum2(B);
    }

    // ---- final states (h1,c1,h2,c2,h3,c3,h4,c4), each [4096,25] ----
    if (write_states) {
        size_t base = (size_t)Tlen * NB;
        const size_t S = (size_t)NB * 25;
#pragma unroll
        for (int k = 0; k < 2; ++k) if (k < nu) {
            const int u = first + k;
            size_t idx = (size_t)gb * 25 + u;
            float h1v = v0r[1 + u];          // buffer 0 holds final self h's
            float h2v = v1r[26 + u];
            float h3v = v2r[26 + u];
            float h4v = v3r[26 + u];
            out[base + 0 * S + idx] = h1v;  out[base + 1 * S + idx] = c[k];
            out[base + 2 * S + idx] = h2v;  out[base + 3 * S + idx] = c[2 + k];
            out[base + 4 * S + idx] = h3v;  out[base + 5 * S + idx] = c[4 + k];
            out[base + 6 * S + idx] = h4v;  out[base + 7 * S + idx] = c[6 + k];
        }
    }
}

extern "C" void kernel_launch(void* const* d_in, const int* in_sizes, int n_in,
                              void* d_out, int out_size) {
    (void)n_in; (void)in_sizes;
    const float* x    = (const float*)d_in[0];
    const float* Wih1 = (const float*)d_in[1];
    const float* Whh1 = (const float*)d_in[2];
    const float* bih1 = (const float*)d_in[3];
    const float* bhh1 = (const float*)d_in[4];
    const float* Wih2 = (const float*)d_in[5];
    const float* Whh2 = (const float*)d_in[6];
    const float* bih2 = (const float*)d_in[7];
    const float* bhh2 = (const float*)d_in[8];
    const float* Wih3 = (const float*)d_in[9];
    const float* Whh3 = (const float*)d_in[10];
    const float* bih3 = (const float*)d_in[11];
    const float* bhh3 = (const float*)d_in[12];
    const float* Wih4 = (const float*)d_in[13];
    const float* Whh4 = (const float*)d_in[14];
    const float* bih4 = (const float*)d_in[15];
    const float* bhh4 = (const float*)d_in[16];
    const float* Wfc  = (const float*)d_in[17];
    const float* bfc  = (const float*)d_in[18];

    int smem_bytes = SMEM_FLOATS * (int)sizeof(float);
    static int configured = -1;
    if (configured != smem_bytes) {
        cudaFuncSetAttribute(lstm_kernel,
                             cudaFuncAttributeMaxDynamicSharedMemorySize, smem_bytes);
        configured = smem_bytes;
    }
    int write_states = (out_size >= Tlen * NB + 8 * NB * 25) ? 1 : 0;

    lstm_kernel<<<NB / 32, NTHR, smem_bytes>>>(
        x, Wih1, Whh1, bih1, bhh1,
        Wih2, Whh2, bih2, bhh2,
        Wih3, Whh3, bih3, bhh3,
        Wih4, Whh4, bih4, bhh4,
        Wfc, bfc, (float*)d_out, write_states);
}

// round 8
// speedup vs baseline: 1.2318x; 1.2318x over previous
#include <cuda_runtime.h>
#include <cstdint>
#include <cstddef>

typedef unsigned long long ull;

#define Tlen   512
#define NB     4096
#define NTHR   512          // 16 warps: 4 per layer, each owns 6-7 units of that layer
#define NTICKS (Tlen + 4)   // layer l does t=T-l; fc does t=T-4

// ---- shared memory layout (float offsets), all 16B-aligned ----
#define W0_OFF    0                    // 100 rows x 28  = 2800  : L1 fused [Wih1|Whh1|pad2]
#define W123_OFF  2800                 // 3 x 100 x 52   = 15600 : L2-4 fused [Wih|0|Whh|0]
#define BIAS_OFF  (W123_OFF + 15600)   // 18400 : [4 layer][25 unit][4 gate] fused bih+bhh
#define WFC_OFF   (BIAS_OFF + 400)     // 18800 : 52-float fc row (W_fc at [26..50])
#define V0_OFF    (WFC_OFF + 52)       // 18852 : [2 buf][32 lane][28]  L1 v-rows
#define V123_OFF  (V0_OFF + 1792)      // 20644 : [3 layer][2 buf][32][52]
#define SMEM_FLOATS (V123_OFF + 9984)  // 30628 floats = 122512 bytes

__device__ __forceinline__ ull pack2(float lo, float hi) {
    return (ull)__float_as_uint(lo) | ((ull)__float_as_uint(hi) << 32);
}
__device__ __forceinline__ float hsum2(ull v) {
    float lo = __uint_as_float((unsigned)v);
    float hi = __uint_as_float((unsigned)(v >> 32));
    return lo + hi;
}
__device__ __forceinline__ void fma2(ull& acc, ull a, ull b) {
    asm("fma.rn.f32x2 %0, %1, %2, %0;" : "+l"(acc) : "l"(a), "l"(b));
}
__device__ __forceinline__ float fast_sig(float x) {
    float e, r;
    asm("ex2.approx.ftz.f32 %0, %1;" : "=f"(e) : "f"(x * -1.4426950408889634f));
    asm("rcp.approx.ftz.f32 %0, %1;" : "=f"(r) : "f"(e + 1.0f));
    return r;
}
__device__ __forceinline__ float fast_tanh(float x) {
    return fmaf(2.0f, fast_sig(2.0f * x), -1.0f);
}

// 4-gate dot products for one unit, v-row already in registers.
template<int NCH>
__device__ __forceinline__ void gates4reg(const ulonglong2* __restrict__ V,
    const float* __restrict__ w0, const float* __restrict__ w1,
    const float* __restrict__ w2, const float* __restrict__ w3,
    float b0, float b1, float b2, float b3,
    float& s0, float& s1, float& s2, float& s3)
{
    ull A0 = pack2(b0, 0.f), B0 = 0ull;
    ull A1 = pack2(b1, 0.f), B1 = 0ull;
    ull A2 = pack2(b2, 0.f), B2 = 0ull;
    ull A3 = pack2(b3, 0.f), B3 = 0ull;
    const ulonglong2* W0 = (const ulonglong2*)w0;
    const ulonglong2* W1 = (const ulonglong2*)w1;
    const ulonglong2* W2 = (const ulonglong2*)w2;
    const ulonglong2* W3 = (const ulonglong2*)w3;
#pragma unroll
    for (int ch = 0; ch < NCH; ++ch) {
        ulonglong2 w;
        w = W0[ch]; fma2(A0, w.x, V[ch].x); fma2(B0, w.y, V[ch].y);
        w = W1[ch]; fma2(A1, w.x, V[ch].x); fma2(B1, w.y, V[ch].y);
        w = W2[ch]; fma2(A2, w.x, V[ch].x); fma2(B2, w.y, V[ch].y);
        w = W3[ch]; fma2(A3, w.x, V[ch].x); fma2(B3, w.y, V[ch].y);
    }
    s0 = hsum2(A0) + hsum2(B0);
    s1 = hsum2(A1) + hsum2(B1);
    s2 = hsum2(A2) + hsum2(B2);
    s3 = hsum2(A3) + hsum2(B3);
}

__global__ void __launch_bounds__(NTHR) lstm_kernel(
    const float* __restrict__ x,
    const float* __restrict__ Wih1, const float* __restrict__ Whh1,
    const float* __restrict__ bih1, const float* __restrict__ bhh1,
    const float* __restrict__ Wih2, const float* __restrict__ Whh2,
    const float* __restrict__ bih2, const float* __restrict__ bhh2,
    const float* __restrict__ Wih3, const float* __restrict__ Whh3,
    const float* __restrict__ bih3, const float* __restrict__ bhh3,
    const float* __restrict__ Wih4, const float* __restrict__ Whh4,
    const float* __restrict__ bih4, const float* __restrict__ bhh4,
    const float* __restrict__ Wfc, const float* __restrict__ bfc,
    float* __restrict__ out, int write_states)
{
    extern __shared__ float smem[];
    const int tid = threadIdx.x;

    // ---- stage fused weights ----
    for (int i = tid; i < 2800; i += NTHR) {
        int g = i / 28, p = i - g * 28;
        float v = 0.f;
        if (p == 0)      v = Wih1[g];
        else if (p < 26) v = Whh1[g * 25 + p - 1];
        smem[W0_OFF + i] = v;
    }
    {
        const float* WihL[3] = {Wih2, Wih3, Wih4};
        const float* WhhL[3] = {Whh2, Whh3, Whh4};
        for (int i = tid; i < 15600; i += NTHR) {
            int l = i / 5200; int r = i - l * 5200;
            int g = r / 52,   p = r - g * 52;
            float v = 0.f;
            if (p < 25)                 v = WihL[l][g * 25 + p];
            else if (p >= 26 && p < 51) v = WhhL[l][g * 25 + p - 26];
            smem[W123_OFF + i] = v;
        }
        const float* bi[4] = {bih1, bih2, bih3, bih4};
        const float* bh[4] = {bhh1, bhh2, bhh3, bhh4};
        // bias as [layer][unit][gate] so one float4 covers a unit's 4 gates
        for (int i = tid; i < 400; i += NTHR) {
            int l = i / 100, r = i - l * 100, u = r >> 2, j = r & 3;
            smem[BIAS_OFF + i] = bi[l][j * 25 + u] + bh[l][j * 25 + u];
        }
    }
    for (int i = tid; i < 52; i += NTHR)
        smem[WFC_OFF + i] = (i >= 26 && i < 51) ? Wfc[i - 26] : 0.f;
    for (int i = tid; i < 1792 + 9984; i += NTHR) smem[V0_OFF + i] = 0.f;
    __syncthreads();

    const int lane  = tid & 31;
    const int wid   = tid >> 5;
    const int layer = wid >> 2;                      // 0..3
    const int wl    = wid & 3;                       // warp-in-layer
    const int first = (wl * 25) >> 2;                // owned units of this layer
    const int nu    = (((wl + 1) * 25) >> 2) - first; // 6,6,6,7
    const int gb    = (blockIdx.x << 5) + lane;      // global batch element

    float xreg = 0.f, bfc_reg = 0.f;
    if (wid == 0) {
        smem[V0_OFF + lane * 28 + 0] = x[gb];        // x(0) -> buffer 0
        xreg = x[(size_t)NB + gb];                   // prefetch x(1)
    }
    if (wid == 1) bfc_reg = bfc[0];
    __syncthreads();

    float c[7], hreg[7];
#pragma unroll
    for (int i = 0; i < 7; ++i) { c[i] = 0.f; hreg[i] = 0.f; }

    float* v0row = smem + V0_OFF + lane * 28;                          // + buf*896
    float* vrow  = (layer == 0) ? v0row
                 : smem + V123_OFF + (layer - 1) * 3328 + lane * 52;   // + buf*1664
    float* child = (layer < 3)
                 ? smem + V123_OFF + layer * 3328 + lane * 52          // + buf*1664
                 : (float*)0;
    const float* biasS = smem + BIAS_OFF + layer * 100;
    const float* wfc   = smem + WFC_OFF;
    const float* v3row = smem + V123_OFF + 2 * 3328 + lane * 52;

    for (int T = 0; T < NTICKS; ++T) {
        const int par = (T + layer) & 1;             // parity of (T - layer)

        // ---- x stager (warp 0): stage x(T+1), prefetch x(T+2) ----
        if (wid == 0) {
            v0row[((T + 1) & 1) * 896 + 0] = xreg;
            int t2 = (T + 2 < Tlen) ? T + 2 : Tlen - 1;
            xreg = x[(size_t)t2 * NB + gb];
        }
        // ---- fc (warp 1): y(T-4) from h4(T-4) in v3 buffer (T+1)&1 ----
        if (wid == 1 && T >= 4) {
            const ulonglong2* V3 = (const ulonglong2*)(v3row + ((T + 1) & 1) * 1664);
            const ulonglong2* WF = (const ulonglong2*)wfc;
            ull A = pack2(bfc_reg, 0.f), B = 0ull;
#pragma unroll
            for (int ch = 6; ch < 13; ++ch) {        // wfc zero outside [26..50]
                ulonglong2 hv = V3[ch]; ulonglong2 w = WF[ch];
                fma2(A, w.x, hv.x); fma2(B, w.y, hv.y);
            }
            out[(size_t)(T - 4) * NB + gb] = hsum2(A) + hsum2(B);
        }

        const bool act = (T >= layer) && (T - layer < Tlen);
        if (act) {
            if (layer == 0) {
                ulonglong2 V[7];
                const ulonglong2* src = (const ulonglong2*)(v0row + par * 896);
#pragma unroll
                for (int ch = 0; ch < 7; ++ch) V[ch] = src[ch];
#pragma unroll
                for (int k = 0; k < 7; ++k) if (k < nu) {
                    const int u = first + k;
                    const float* wr = smem + W0_OFF + u * 28;
                    float4 bb = *(const float4*)(biasS + u * 4);
                    float s0, s1, s2, s3;
                    gates4reg<7>(V, wr, wr + 700, wr + 1400, wr + 2100,
                                 bb.x, bb.y, bb.z, bb.w, s0, s1, s2, s3);
                    float fi = fast_sig(s0), ff = fast_sig(s1);
                    float fg = fast_tanh(s2), fo = fast_sig(s3);
                    c[k] = fmaf(ff, c[k], fi * fg);
                    float h = fo * fast_tanh(c[k]);
                    hreg[k] = h;
                    v0row[(par ^ 1) * 896 + 1 + u] = h;     // self, next tick
                    child[par * 1664 + u]          = h;     // layer 1, next tick
                }
            } else {
                ulonglong2 V[13];
                const ulonglong2* src = (const ulonglong2*)(vrow + par * 1664);
#pragma unroll
                for (int ch = 0; ch < 13; ++ch) V[ch] = src[ch];
#pragma unroll
                for (int k = 0; k < 7; ++k) if (k < nu) {
                    const int u = first + k;
                    const float* wr = smem + W123_OFF + (layer - 1) * 5200 + u * 52;
                    float4 bb = *(const float4*)(biasS + u * 4);
                    float s0, s1, s2, s3;
                    gates4reg<13>(V, wr, wr + 1300, wr + 2600, wr + 3900,
                                  bb.x, bb.y, bb.z, bb.w, s0, s1, s2, s3);
                    float fi = fast_sig(s0), ff = fast_sig(s1);
                    float fg = fast_tanh(s2), fo = fast_sig(s3);
                    c[k] = fmaf(ff, c[k], fi * fg);
                    float h = fo * fast_tanh(c[k]);
                    hreg[k] = h;
                    vrow[(par ^ 1) * 1664 + 26 + u] = h;    // self, next tick
                    if (layer < 3) child[par * 1664 + u] = h;
                }
            }
        }
        __syncthreads();
    }

    // ---- final states (h1,c1,h2,c2,h3,c3,h4,c4), each [4096,25] ----
    if (write_states) {
        size_t base = (size_t)Tlen * NB;
        const size_t S = (size_t)NB * 25;
#pragma unroll
        for (int k = 0; k < 7; ++k) if (k < nu) {
            const int u = first + k;
            size_t idx = (size_t)gb * 25 + u;
            out[base + (size_t)(2 * layer) * S + idx]     = hreg[k];
            out[base + (size_t)(2 * layer + 1) * S + idx] = c[k];
        }
    }
}

extern "C" void kernel_launch(void* const* d_in, const int* in_sizes, int n_in,
                              void* d_out, int out_size) {
    (void)n_in; (void)in_sizes;
    const float* x    = (const float*)d_in[0];
    const float* Wih1 = (const float*)d_in[1];
    const float* Whh1 = (const float*)d_in[2];
    const float* bih1 = (const float*)d_in[3];
    const float* bhh1 = (const float*)d_in[4];
    const float* Wih2 = (const float*)d_in[5];
    const float* Whh2 = (const float*)d_in[6];
    const float* bih2 = (const float*)d_in[7];
    const float* bhh2 = (const float*)d_in[8];
    const float* Wih3 = (const float*)d_in[9];
    const float* Whh3 = (const float*)d_in[10];
    const float* bih3 = (const float*)d_in[11];
    const float* bhh3 = (const float*)d_in[12];
    const float* Wih4 = (const float*)d_in[13];
    const float* Whh4 = (const float*)d_in[14];
    const float* bih4 = (const float*)d_in[15];
    const float* bhh4 = (const float*)d_in[16];
    const float* Wfc  = (const float*)d_in[17];
    const float* bfc  = (const float*)d_in[18];

    int smem_bytes = SMEM_FLOATS * (int)sizeof(float);
    static int configured = -1;
    if (configured != smem_bytes) {
        cudaFuncSetAttribute(lstm_kernel,
                             cudaFuncAttributeMaxDynamicSharedMemorySize, smem_bytes);
        configured = smem_bytes;
    }
    int write_states = (out_size >= Tlen * NB + 8 * NB * 25) ? 1 : 0;

    lstm_kernel<<<NB / 32, NTHR, smem_bytes>>>(
        x, Wih1, Whh1, bih1, bhh1,
        Wih2, Whh2, bih2, bhh2,
        Wih3, Whh3, bih3, bhh3,
        Wih4, Whh4, bih4, bhh4,
        Wfc, bfc, (float*)d_out, write_states);
}